// round 1
// baseline (speedup 1.0000x reference)
#include <cuda_runtime.h>
#include <math.h>

// Problem constants
#define BB 4
#define LS 1024
#define DMOD 1024
#define NH 16
#define DKH 64
#define DVH 64

#define OUT_ELEMS ((long long)BB * LS * DMOD)            // 4194304
#define ATT_ELEMS ((long long)BB * NH * LS * LS)         // 67108864

// -------------------- scratch (device globals; no allocation allowed) ------
__device__ float g_qh[BB * NH * LS * DKH];    // [B,H,L,DK]
__device__ float g_kh[BB * NH * LS * DKH];
__device__ float g_vh[BB * NH * LS * DVH];
__device__ float g_ctx[BB * LS * NH * DVH];   // [B,L,H*DV]
__device__ float g_fc[BB * LS * DMOD];        // pre-LN fc output
__device__ float g_attn[(size_t)BB * NH * LS * LS];   // 256MB attn scratch
__device__ float g_outs[BB * LS * DMOD];      // fallback out sink

// ---------------------------------------------------------------------------
// Generic NT GEMM with bias:  C[r,n] = sum_k A[r,k] * W[n,k] + bias[n]
// A: [R, K] row-major, W: [N, K] row-major.
// Output written in [B, H, L, Dhead] layout where r = b*LS + l, n = h*Dhead + d,
// H = N / Dhead.  (Dhead == N gives plain row-major [R, N].)
// Tiles: 64x64, BK=16, 256 threads, 4x4 micro-tile.
// ---------------------------------------------------------------------------
__global__ void gemm_nt_bias(const float* __restrict__ A,
                             const float* __restrict__ W,
                             const float* __restrict__ bias,
                             float* __restrict__ out,
                             int K, int N, int Dhead)
{
    __shared__ float As[16][65];
    __shared__ float Ws[16][65];

    const int t  = threadIdx.x;
    const int tx = t & 15;
    const int ty = t >> 4;
    const int rowBase = blockIdx.y * 64;
    const int colBase = blockIdx.x * 64;

    float acc[4][4];
#pragma unroll
    for (int p = 0; p < 4; p++)
#pragma unroll
        for (int q = 0; q < 4; q++) acc[p][q] = 0.f;

    const int li = t >> 4;   // 0..15
    const int lk = t & 15;   // 0..15

    for (int k0 = 0; k0 < K; k0 += 16) {
#pragma unroll
        for (int j = 0; j < 4; j++) {
            As[lk][li + 16 * j] = A[(size_t)(rowBase + li + 16 * j) * K + k0 + lk];
            Ws[lk][li + 16 * j] = W[(size_t)(colBase + li + 16 * j) * K + k0 + lk];
        }
        __syncthreads();
#pragma unroll
        for (int kk = 0; kk < 16; kk++) {
            float a[4], w[4];
#pragma unroll
            for (int p = 0; p < 4; p++) a[p] = As[kk][ty * 4 + p];
#pragma unroll
            for (int q = 0; q < 4; q++) w[q] = Ws[kk][tx * 4 + q];
#pragma unroll
            for (int p = 0; p < 4; p++)
#pragma unroll
                for (int q = 0; q < 4; q++) acc[p][q] += a[p] * w[q];
        }
        __syncthreads();
    }

    const int H = N / Dhead;
#pragma unroll
    for (int p = 0; p < 4; p++) {
        const int r = rowBase + ty * 4 + p;
        const int b = r / LS, l = r % LS;
#pragma unroll
        for (int q = 0; q < 4; q++) {
            const int n = colBase + tx * 4 + q;
            const int h = n / Dhead, d = n % Dhead;
            const size_t dst = (((size_t)b * H + h) * LS + l) * Dhead + d;
            out[dst] = acc[p][q] + bias[n];
        }
    }
}

// ---------------------------------------------------------------------------
// Scores:  S[z,q,k] = (Qh[z,q,:] . Kh[z,k,:]) * 0.125 * gate[z,q,k],
//          then -inf where mask[b,q,k] > 0.   z = b*NH + h.
// ---------------------------------------------------------------------------
__global__ void scores_kernel(const float* __restrict__ gate,
                              const int*   __restrict__ mask,
                              float* __restrict__ attn)
{
    __shared__ float Qs[16][65];
    __shared__ float Ks[16][65];

    const int z = blockIdx.z;
    const int b = z / NH;
    const float* Q  = g_qh + (size_t)z * LS * DKH;
    const float* Kp = g_kh + (size_t)z * LS * DKH;

    const int t  = threadIdx.x;
    const int tx = t & 15;
    const int ty = t >> 4;
    const int rowBase = blockIdx.y * 64;   // q tile
    const int colBase = blockIdx.x * 64;   // k tile

    float acc[4][4];
#pragma unroll
    for (int p = 0; p < 4; p++)
#pragma unroll
        for (int q = 0; q < 4; q++) acc[p][q] = 0.f;

    const int li = t >> 4, lk = t & 15;

    for (int k0 = 0; k0 < DKH; k0 += 16) {
#pragma unroll
        for (int j = 0; j < 4; j++) {
            Qs[lk][li + 16 * j] = Q[(size_t)(rowBase + li + 16 * j) * DKH + k0 + lk];
            Ks[lk][li + 16 * j] = Kp[(size_t)(colBase + li + 16 * j) * DKH + k0 + lk];
        }
        __syncthreads();
#pragma unroll
        for (int kk = 0; kk < 16; kk++) {
            float a[4], w[4];
#pragma unroll
            for (int p = 0; p < 4; p++) a[p] = Qs[kk][ty * 4 + p];
#pragma unroll
            for (int q = 0; q < 4; q++) w[q] = Ks[kk][tx * 4 + q];
#pragma unroll
            for (int p = 0; p < 4; p++)
#pragma unroll
                for (int q = 0; q < 4; q++) acc[p][q] += a[p] * w[q];
        }
        __syncthreads();
    }

#pragma unroll
    for (int p = 0; p < 4; p++) {
        const int qi = rowBase + ty * 4 + p;
#pragma unroll
        for (int q = 0; q < 4; q++) {
            const int ki = colBase + tx * 4 + q;
            const size_t gi = ((size_t)z * LS + qi) * LS + ki;
            const size_t mi = ((size_t)b * LS + qi) * LS + ki;
            float val = acc[p][q] * 0.125f * gate[gi];
            if (mask[mi] > 0) val = -INFINITY;
            attn[gi] = val;
        }
    }
}

// ---------------------------------------------------------------------------
// Row softmax in place over last dim (1024).  grid (1024, 64), block 256.
// ---------------------------------------------------------------------------
__global__ void softmax_kernel(float* __restrict__ attn)
{
    __shared__ float red[256];
    const size_t row = (size_t)blockIdx.y * LS + blockIdx.x;
    float* p = attn + row * LS;
    const int t = threadIdx.x;

    float v[4];
    float m = -INFINITY;
#pragma unroll
    for (int j = 0; j < 4; j++) {
        v[j] = p[t + 256 * j];
        m = fmaxf(m, v[j]);
    }
    red[t] = m; __syncthreads();
    for (int s = 128; s > 0; s >>= 1) {
        if (t < s) red[t] = fmaxf(red[t], red[t + s]);
        __syncthreads();
    }
    m = red[0];
    __syncthreads();

    float sum = 0.f;
#pragma unroll
    for (int j = 0; j < 4; j++) {
        v[j] = expf(v[j] - m);
        sum += v[j];
    }
    red[t] = sum; __syncthreads();
    for (int s = 128; s > 0; s >>= 1) {
        if (t < s) red[t] += red[t + s];
        __syncthreads();
    }
    const float inv = 1.f / red[0];
#pragma unroll
    for (int j = 0; j < 4; j++) p[t + 256 * j] = v[j] * inv;
}

// ---------------------------------------------------------------------------
// AV:  ctx[b, q, h*64 + d] = sum_k P[z,q,k] * Vh[z,k,d].   grid (1, 16, 64).
// ---------------------------------------------------------------------------
__global__ void av_kernel(const float* __restrict__ attn)
{
    __shared__ float Ps[16][65];
    __shared__ float Vs[16][65];

    const int z = blockIdx.z;
    const int b = z / NH, h = z % NH;
    const float* P = attn + (size_t)z * LS * LS;
    const float* V = g_vh + (size_t)z * LS * DVH;

    const int t  = threadIdx.x;
    const int tx = t & 15;
    const int ty = t >> 4;
    const int rowBase = blockIdx.y * 64;

    float acc[4][4];
#pragma unroll
    for (int p = 0; p < 4; p++)
#pragma unroll
        for (int q = 0; q < 4; q++) acc[p][q] = 0.f;

    const int li = t >> 4, lk = t & 15;
    const int vj = t & 63, vk = t >> 6;

    for (int k0 = 0; k0 < LS; k0 += 16) {
#pragma unroll
        for (int j = 0; j < 4; j++)
            Ps[lk][li + 16 * j] = P[(size_t)(rowBase + li + 16 * j) * LS + k0 + lk];
#pragma unroll
        for (int r = 0; r < 4; r++)
            Vs[vk + 4 * r][vj] = V[(size_t)(k0 + vk + 4 * r) * DVH + vj];
        __syncthreads();
#pragma unroll
        for (int kk = 0; kk < 16; kk++) {
            float a[4], w[4];
#pragma unroll
            for (int p = 0; p < 4; p++) a[p] = Ps[kk][ty * 4 + p];
#pragma unroll
            for (int q = 0; q < 4; q++) w[q] = Vs[kk][tx * 4 + q];
#pragma unroll
            for (int p = 0; p < 4; p++)
#pragma unroll
                for (int q = 0; q < 4; q++) acc[p][q] += a[p] * w[q];
        }
        __syncthreads();
    }

#pragma unroll
    for (int p = 0; p < 4; p++) {
        const int qi = rowBase + ty * 4 + p;
#pragma unroll
        for (int q = 0; q < 4; q++) {
            const int d = tx * 4 + q;
            g_ctx[((size_t)b * LS + qi) * (NH * DVH) + h * DVH + d] = acc[p][q];
        }
    }
}

// ---------------------------------------------------------------------------
// Residual + LayerNorm.  grid 4096, block 256.
// ---------------------------------------------------------------------------
__global__ void ln_kernel(const float* __restrict__ resid,
                          const float* __restrict__ gamma,
                          const float* __restrict__ beta,
                          float* __restrict__ out)
{
    __shared__ float red[256];
    const int r = blockIdx.x;
    const float* xf = g_fc + (size_t)r * DMOD;
    const float* rz = resid + (size_t)r * DMOD;
    const int t = threadIdx.x;

    float v[4];
    float sum = 0.f;
#pragma unroll
    for (int j = 0; j < 4; j++) {
        v[j] = xf[t + 256 * j] + rz[t + 256 * j];
        sum += v[j];
    }
    red[t] = sum; __syncthreads();
    for (int s = 128; s > 0; s >>= 1) {
        if (t < s) red[t] += red[t + s];
        __syncthreads();
    }
    const float mu = red[0] * (1.f / DMOD);
    __syncthreads();

    float vs = 0.f;
#pragma unroll
    for (int j = 0; j < 4; j++) {
        const float d = v[j] - mu;
        vs += d * d;
    }
    red[t] = vs; __syncthreads();
    for (int s = 128; s > 0; s >>= 1) {
        if (t < s) red[t] += red[t + s];
        __syncthreads();
    }
    const float var = red[0] * (1.f / DMOD);
    const float inv = 1.f / sqrtf(var + 1e-5f);
#pragma unroll
    for (int j = 0; j < 4; j++) {
        const int c = t + 256 * j;
        out[(size_t)r * DMOD + c] = (v[j] - mu) * inv * gamma[c] + beta[c];
    }
}

// ---------------------------------------------------------------------------
extern "C" void kernel_launch(void* const* d_in, const int* in_sizes, int n_in,
                              void* d_out, int out_size)
{
    const float* q    = (const float*)d_in[0];
    const float* k    = (const float*)d_in[1];
    const float* v    = (const float*)d_in[2];
    const int*   mask = (const int*)  d_in[3];
    const float* gate = (const float*)d_in[4];
    const float* w_q  = (const float*)d_in[5];
    const float* b_q  = (const float*)d_in[6];
    const float* w_k  = (const float*)d_in[7];
    const float* b_k  = (const float*)d_in[8];
    const float* w_v  = (const float*)d_in[9];
    const float* b_v  = (const float*)d_in[10];
    const float* w_fc = (const float*)d_in[11];
    const float* b_fc = (const float*)d_in[12];
    const float* ln_g = (const float*)d_in[13];
    const float* ln_b = (const float*)d_in[14];
    float* out = (float*)d_out;

    float *p_qh, *p_kh, *p_vh, *p_ctx, *p_fc, *p_attn_s, *p_outs;
    cudaGetSymbolAddress((void**)&p_qh,     g_qh);
    cudaGetSymbolAddress((void**)&p_kh,     g_kh);
    cudaGetSymbolAddress((void**)&p_vh,     g_vh);
    cudaGetSymbolAddress((void**)&p_ctx,    g_ctx);
    cudaGetSymbolAddress((void**)&p_fc,     g_fc);
    cudaGetSymbolAddress((void**)&p_attn_s, g_attn);
    cudaGetSymbolAddress((void**)&p_outs,   g_outs);

    // Reference returns (out, attn).  Resolve destinations from out_size.
    float* attn_ptr;
    float* out_ptr;
    const long long osz = (long long)out_size;
    if (osz >= OUT_ELEMS + ATT_ELEMS) {        // concatenated tuple
        out_ptr  = out;
        attn_ptr = out + OUT_ELEMS;
    } else if (osz >= ATT_ELEMS) {             // attn only
        out_ptr  = p_outs;
        attn_ptr = out;
    } else {                                   // out only
        out_ptr  = out;
        attn_ptr = p_attn_s;
    }

    // 1) QKV projections
    gemm_nt_bias<<<dim3(16, 64), 256>>>(q, w_q, b_q, p_qh, DMOD, NH * DKH, DKH);
    gemm_nt_bias<<<dim3(16, 64), 256>>>(k, w_k, b_k, p_kh, DMOD, NH * DKH, DKH);
    gemm_nt_bias<<<dim3(16, 64), 256>>>(v, w_v, b_v, p_vh, DMOD, NH * DVH, DVH);

    // 2) Scores with scale*gate*mask epilogue
    scores_kernel<<<dim3(16, 16, BB * NH), 256>>>(gate, mask, attn_ptr);

    // 3) Row softmax in place
    softmax_kernel<<<dim3(LS, BB * NH), 256>>>(attn_ptr);

    // 4) AV -> ctx [B, L, H*DV]
    av_kernel<<<dim3(1, 16, BB * NH), 256>>>(attn_ptr);

    // 5) FC projection (plain row-major output via Dhead == N)
    gemm_nt_bias<<<dim3(16, 64), 256>>>(p_ctx, w_fc, b_fc, p_fc, DMOD, DMOD, DMOD);

    // 6) Residual + LayerNorm -> final out
    ln_kernel<<<4096, 256>>>(q, ln_g, ln_b, out_ptr);
}

// round 2
// speedup vs baseline: 2.8757x; 2.8757x over previous
#include <cuda_runtime.h>
#include <math.h>

// Problem constants
#define BB 4
#define LS 1024
#define DMOD 1024
#define NH 16
#define DKH 64
#define DVH 64
#define ZH (BB * NH)

#define OUT_ELEMS ((long long)BB * LS * DMOD)            // 4194304
#define ATT_ELEMS ((long long)ZH * LS * LS)              // 67108864

// -------------------- scratch (device globals; no allocation allowed) ------
__device__ float g_qh[ZH * LS * DKH];        // [B,H,L,DK]
__device__ float g_kh[ZH * LS * DKH];
__device__ float g_vh[ZH * LS * DVH];
__device__ float g_ctx[BB * LS * NH * DVH];  // [B,L,H*DV]
__device__ float g_fc[BB * LS * DMOD];       // pre-LN fc output
__device__ float g_part[(size_t)ZH * LS * 8];// per-(z,row) partial exp-sums, 8 col tiles
__device__ float g_invsum[ZH * LS];          // 1 / rowsum
__device__ float g_attn[(size_t)ZH * LS * LS]; // 256MB attn scratch (fallback)
__device__ float g_outs[BB * LS * DMOD];     // fallback out sink

// ---------------------------------------------------------------------------
// helpers: tf32 convert + m16n8k8 tf32 mma
// ---------------------------------------------------------------------------
__device__ __forceinline__ unsigned f2tf(float f) {
    unsigned r;
    asm("cvt.rna.tf32.f32 %0, %1;" : "=r"(r) : "f"(f));
    return r;
}

__device__ __forceinline__ void mma8(float& c0, float& c1, float& c2, float& c3,
                                     unsigned a0, unsigned a1, unsigned a2, unsigned a3,
                                     unsigned b0, unsigned b1) {
    asm volatile(
        "mma.sync.aligned.m16n8k8.row.col.f32.tf32.tf32.f32 "
        "{%0,%1,%2,%3}, {%4,%5,%6,%7}, {%8,%9}, {%0,%1,%2,%3};\n"
        : "+f"(c0), "+f"(c1), "+f"(c2), "+f"(c3)
        : "r"(a0), "r"(a1), "r"(a2), "r"(a3), "r"(b0), "r"(b1));
}

// ---------------------------------------------------------------------------
// TF32 NT GEMM + bias:  C[r,n] = sum_k A[r,k] * W[n,k] + bias[n]
// A [M,K] row-major (ld=K), W [N,K] row-major (ld=K).
// Output in [B,H,L,Dhead] layout (Dhead==N gives plain row-major).
// Block tile 128x128, BK=32, 8 warps (2m x 4n), warp tile 64x32.
// ---------------------------------------------------------------------------
__global__ void __launch_bounds__(256)
gemm_tf32(const float* __restrict__ A, const float* __restrict__ W,
          const float* __restrict__ bias, float* __restrict__ out,
          int K, int N, int Dhead)
{
    __shared__ unsigned As[128 * 36];
    __shared__ unsigned Ws[128 * 36];

    const int t = threadIdx.x, lane = t & 31, w = t >> 5;
    const int wm = w >> 2, wn = w & 3;          // 2 x 4 warps
    const int g = lane >> 2, tg = lane & 3;
    const int rowBase = blockIdx.y * 128;
    const int colBase = blockIdx.x * 128;

    float c[4][4][4];
#pragma unroll
    for (int mt = 0; mt < 4; mt++)
#pragma unroll
        for (int nt = 0; nt < 4; nt++)
#pragma unroll
            for (int i = 0; i < 4; i++) c[mt][nt][i] = 0.f;

    for (int k0 = 0; k0 < K; k0 += 32) {
#pragma unroll
        for (int i = 0; i < 4; i++) {
            const int idx = t + 256 * i;
            const int row = idx >> 3, c4 = (idx & 7) * 4;
            float4 av = *(const float4*)(A + (size_t)(rowBase + row) * K + k0 + c4);
            uint4 ua = make_uint4(f2tf(av.x), f2tf(av.y), f2tf(av.z), f2tf(av.w));
            *(uint4*)&As[row * 36 + c4] = ua;
            float4 wv = *(const float4*)(W + (size_t)(colBase + row) * K + k0 + c4);
            uint4 uw = make_uint4(f2tf(wv.x), f2tf(wv.y), f2tf(wv.z), f2tf(wv.w));
            *(uint4*)&Ws[row * 36 + c4] = uw;
        }
        __syncthreads();
#pragma unroll
        for (int ks = 0; ks < 4; ks++) {
            const int kk = ks * 8;
            unsigned a[4][4], b[4][2];
#pragma unroll
            for (int mt = 0; mt < 4; mt++) {
                const int r = (wm * 64 + mt * 16 + g) * 36 + kk + tg;
                a[mt][0] = As[r];            a[mt][1] = As[r + 8 * 36];
                a[mt][2] = As[r + 4];        a[mt][3] = As[r + 8 * 36 + 4];
            }
#pragma unroll
            for (int nt = 0; nt < 4; nt++) {
                const int r = (wn * 32 + nt * 8 + g) * 36 + kk + tg;
                b[nt][0] = Ws[r];            b[nt][1] = Ws[r + 4];
            }
#pragma unroll
            for (int mt = 0; mt < 4; mt++)
#pragma unroll
                for (int nt = 0; nt < 4; nt++)
                    mma8(c[mt][nt][0], c[mt][nt][1], c[mt][nt][2], c[mt][nt][3],
                         a[mt][0], a[mt][1], a[mt][2], a[mt][3],
                         b[nt][0], b[nt][1]);
        }
        __syncthreads();
    }

    const int H = N / Dhead;
#pragma unroll
    for (int mt = 0; mt < 4; mt++) {
        const int rr = rowBase + wm * 64 + mt * 16 + g;
        const int b_ = rr >> 10, l = rr & 1023;
#pragma unroll
        for (int nt = 0; nt < 4; nt++) {
            const int cc = colBase + wn * 32 + nt * 8 + 2 * tg;
            const int h = cc / Dhead, d = cc % Dhead;
            const size_t dst = (((size_t)(b_ * H + h)) * LS + l) * Dhead + d;
            const float b0 = bias[cc], b1 = bias[cc + 1];
            *(float2*)&out[dst]             = make_float2(c[mt][nt][0] + b0, c[mt][nt][1] + b1);
            *(float2*)&out[dst + 8 * Dhead] = make_float2(c[mt][nt][2] + b0, c[mt][nt][3] + b1);
        }
    }
}

// ---------------------------------------------------------------------------
// Scores (tf32) + fused masked-gated exp + deterministic row-sum partials.
// S = (Q K^T) * 0.125 * gate ; masked -> 0 ; attn <- exp(S) (UNNORMALIZED).
// part[z, row, colTile] = partial row sum. No max-subtraction (|logit| small).
// grid (8, 8, 64), block 256.
// ---------------------------------------------------------------------------
__global__ void __launch_bounds__(256)
scores_tf32(const float* __restrict__ qh, const float* __restrict__ kh,
            const float* __restrict__ gate, const int* __restrict__ mask,
            float* __restrict__ attn, float* __restrict__ part)
{
    __shared__ unsigned As[128 * 36];
    __shared__ unsigned Ws[128 * 36];
    __shared__ float psh[4][128];

    const int t = threadIdx.x, lane = t & 31, w = t >> 5;
    const int wm = w >> 2, wn = w & 3;
    const int g = lane >> 2, tg = lane & 3;
    const int z = blockIdx.z, b = z >> 4;
    const int rowBase = blockIdx.y * 128;
    const int colBase = blockIdx.x * 128;
    const float* Q  = qh + (size_t)z * LS * DKH;
    const float* Kp = kh + (size_t)z * LS * DKH;

    float c[4][4][4];
#pragma unroll
    for (int mt = 0; mt < 4; mt++)
#pragma unroll
        for (int nt = 0; nt < 4; nt++)
#pragma unroll
            for (int i = 0; i < 4; i++) c[mt][nt][i] = 0.f;

#pragma unroll
    for (int k0 = 0; k0 < DKH; k0 += 32) {
#pragma unroll
        for (int i = 0; i < 4; i++) {
            const int idx = t + 256 * i;
            const int row = idx >> 3, c4 = (idx & 7) * 4;
            float4 av = *(const float4*)(Q + (size_t)(rowBase + row) * DKH + k0 + c4);
            *(uint4*)&As[row * 36 + c4] = make_uint4(f2tf(av.x), f2tf(av.y), f2tf(av.z), f2tf(av.w));
            float4 wv = *(const float4*)(Kp + (size_t)(colBase + row) * DKH + k0 + c4);
            *(uint4*)&Ws[row * 36 + c4] = make_uint4(f2tf(wv.x), f2tf(wv.y), f2tf(wv.z), f2tf(wv.w));
        }
        __syncthreads();
#pragma unroll
        for (int ks = 0; ks < 4; ks++) {
            const int kk = ks * 8;
            unsigned a[4][4], bfr[4][2];
#pragma unroll
            for (int mt = 0; mt < 4; mt++) {
                const int r = (wm * 64 + mt * 16 + g) * 36 + kk + tg;
                a[mt][0] = As[r];     a[mt][1] = As[r + 8 * 36];
                a[mt][2] = As[r + 4]; a[mt][3] = As[r + 8 * 36 + 4];
            }
#pragma unroll
            for (int nt = 0; nt < 4; nt++) {
                const int r = (wn * 32 + nt * 8 + g) * 36 + kk + tg;
                bfr[nt][0] = Ws[r];   bfr[nt][1] = Ws[r + 4];
            }
#pragma unroll
            for (int mt = 0; mt < 4; mt++)
#pragma unroll
                for (int nt = 0; nt < 4; nt++)
                    mma8(c[mt][nt][0], c[mt][nt][1], c[mt][nt][2], c[mt][nt][3],
                         a[mt][0], a[mt][1], a[mt][2], a[mt][3],
                         bfr[nt][0], bfr[nt][1]);
        }
        __syncthreads();
    }

    // epilogue: gate * scale, mask, exp, write attn, accumulate row sums
    float rs[4][2];
#pragma unroll
    for (int mt = 0; mt < 4; mt++) { rs[mt][0] = 0.f; rs[mt][1] = 0.f; }

#pragma unroll
    for (int mt = 0; mt < 4; mt++) {
        const int rr = rowBase + wm * 64 + mt * 16 + g;
#pragma unroll
        for (int nt = 0; nt < 4; nt++) {
            const int cc = colBase + wn * 32 + nt * 8 + 2 * tg;
            const size_t base  = (size_t)z * LS * LS + (size_t)rr * LS + cc;
            const size_t mbase = (size_t)b * LS * LS + (size_t)rr * LS + cc;
            {
                float2 gv = *(const float2*)&gate[base];
                int2   mv = *(const int2*)&mask[mbase];
                float v0 = (mv.x > 0) ? 0.f : __expf(c[mt][nt][0] * 0.125f * gv.x);
                float v1 = (mv.y > 0) ? 0.f : __expf(c[mt][nt][1] * 0.125f * gv.y);
                *(float2*)&attn[base] = make_float2(v0, v1);
                rs[mt][0] += v0 + v1;
            }
            {
                float2 gv = *(const float2*)&gate[base + 8 * LS];
                int2   mv = *(const int2*)&mask[mbase + 8 * LS];
                float v2 = (mv.x > 0) ? 0.f : __expf(c[mt][nt][2] * 0.125f * gv.x);
                float v3 = (mv.y > 0) ? 0.f : __expf(c[mt][nt][3] * 0.125f * gv.y);
                *(float2*)&attn[base + 8 * LS] = make_float2(v2, v3);
                rs[mt][1] += v2 + v3;
            }
        }
    }

    // deterministic reduction: sum over the 4 lanes of each quad (tg), then over wn
#pragma unroll
    for (int mt = 0; mt < 4; mt++) {
#pragma unroll
        for (int hf = 0; hf < 2; hf++) {
            float v = rs[mt][hf];
            v += __shfl_xor_sync(0xffffffffu, v, 1);
            v += __shfl_xor_sync(0xffffffffu, v, 2);
            rs[mt][hf] = v;
        }
    }
    if (tg == 0) {
#pragma unroll
        for (int mt = 0; mt < 4; mt++) {
            psh[wn][wm * 64 + mt * 16 + g]     = rs[mt][0];
            psh[wn][wm * 64 + mt * 16 + g + 8] = rs[mt][1];
        }
    }
    __syncthreads();
    if (t < 128) {
        const float s = psh[0][t] + psh[1][t] + psh[2][t] + psh[3][t];
        part[((size_t)z * LS + rowBase + t) * 8 + blockIdx.x] = s;
    }
}

// ---------------------------------------------------------------------------
// Reduce 8 partials -> 1/rowsum.  grid 256, block 256.
// ---------------------------------------------------------------------------
__global__ void reduce_inv(const float* __restrict__ part, float* __restrict__ invsum)
{
    const int i = blockIdx.x * 256 + threadIdx.x;   // 65536 rows
    float s = 0.f;
#pragma unroll
    for (int j = 0; j < 8; j++) s += part[(size_t)i * 8 + j];
    invsum[i] = 1.f / s;
}

// ---------------------------------------------------------------------------
// AV (tf32): normalizes P during load (and writes normalized attn in place),
// then ctx[b,q,h*64+d] = sum_k Pn[q,k] V[k,d].
// Block tile 128(m) x 64(n), BK=32, 8 warps (4m x 2n), warp tile 32x32.
// grid (8, 64), block 256.
// ---------------------------------------------------------------------------
__global__ void __launch_bounds__(256)
av_tf32(float* __restrict__ attn, const float* __restrict__ invsum,
        const float* __restrict__ vh, float* __restrict__ ctx)
{
    __shared__ unsigned Ps[128 * 36];
    __shared__ unsigned Vs[32 * 72];
    __shared__ float invsh[128];

    const int t = threadIdx.x, lane = t & 31, w = t >> 5;
    const int wm = w >> 1, wn = w & 1;          // 4 x 2 warps
    const int g = lane >> 2, tg = lane & 3;
    const int z = blockIdx.y, b = z >> 4, h = z & 15;
    const int rowBase = blockIdx.x * 128;
    float* P = attn + (size_t)z * LS * LS;
    const float* V = vh + (size_t)z * LS * DVH;

    if (t < 128) invsh[t] = invsum[z * LS + rowBase + t];
    __syncthreads();

    float c[2][4][4];
#pragma unroll
    for (int mt = 0; mt < 2; mt++)
#pragma unroll
        for (int nt = 0; nt < 4; nt++)
#pragma unroll
            for (int i = 0; i < 4; i++) c[mt][nt][i] = 0.f;

    for (int k0 = 0; k0 < LS; k0 += 32) {
        // stage P (normalize + writeback) : 128 x 32
#pragma unroll
        for (int i = 0; i < 4; i++) {
            const int idx = t + 256 * i;
            const int row = idx >> 3, c4 = (idx & 7) * 4;
            const size_t ga = (size_t)(rowBase + row) * LS + k0 + c4;
            float4 pv = *(const float4*)(P + ga);
            const float inv = invsh[row];
            pv.x *= inv; pv.y *= inv; pv.z *= inv; pv.w *= inv;
            *(float4*)(P + ga) = pv;   // normalized attn output (in place)
            *(uint4*)&Ps[row * 36 + c4] = make_uint4(f2tf(pv.x), f2tf(pv.y), f2tf(pv.z), f2tf(pv.w));
        }
        // stage V : 32 x 64
#pragma unroll
        for (int i = 0; i < 2; i++) {
            const int idx = t + 256 * i;
            const int vr = idx >> 4, c4 = (idx & 15) * 4;
            float4 vv = *(const float4*)(V + (size_t)(k0 + vr) * DVH + c4);
            *(uint4*)&Vs[vr * 72 + c4] = make_uint4(f2tf(vv.x), f2tf(vv.y), f2tf(vv.z), f2tf(vv.w));
        }
        __syncthreads();
#pragma unroll
        for (int ks = 0; ks < 4; ks++) {
            const int kk = ks * 8;
            unsigned a[2][4], bfr[4][2];
#pragma unroll
            for (int mt = 0; mt < 2; mt++) {
                const int r = (wm * 32 + mt * 16 + g) * 36 + kk + tg;
                a[mt][0] = Ps[r];     a[mt][1] = Ps[r + 8 * 36];
                a[mt][2] = Ps[r + 4]; a[mt][3] = Ps[r + 8 * 36 + 4];
            }
#pragma unroll
            for (int nt = 0; nt < 4; nt++) {
                const int col = wn * 32 + nt * 8 + g;
                bfr[nt][0] = Vs[(kk + tg) * 72 + col];
                bfr[nt][1] = Vs[(kk + tg + 4) * 72 + col];
            }
#pragma unroll
            for (int mt = 0; mt < 2; mt++)
#pragma unroll
                for (int nt = 0; nt < 4; nt++)
                    mma8(c[mt][nt][0], c[mt][nt][1], c[mt][nt][2], c[mt][nt][3],
                         a[mt][0], a[mt][1], a[mt][2], a[mt][3],
                         bfr[nt][0], bfr[nt][1]);
        }
        __syncthreads();
    }

#pragma unroll
    for (int mt = 0; mt < 2; mt++) {
        const int q = rowBase + wm * 32 + mt * 16 + g;
#pragma unroll
        for (int nt = 0; nt < 4; nt++) {
            const int d = wn * 32 + nt * 8 + 2 * tg;
            const size_t dst = ((size_t)(b * LS + q)) * DMOD + h * 64 + d;
            *(float2*)&ctx[dst]            = make_float2(c[mt][nt][0], c[mt][nt][1]);
            *(float2*)&ctx[dst + 8 * DMOD] = make_float2(c[mt][nt][2], c[mt][nt][3]);
        }
    }
}

// ---------------------------------------------------------------------------
// Residual + LayerNorm.  grid 4096, block 256.
// ---------------------------------------------------------------------------
__global__ void ln_kernel(const float* __restrict__ resid,
                          const float* __restrict__ gamma,
                          const float* __restrict__ beta,
                          const float* __restrict__ fcv,
                          float* __restrict__ out)
{
    __shared__ float red[256];
    const int r = blockIdx.x;
    const float* xf = fcv + (size_t)r * DMOD;
    const float* rz = resid + (size_t)r * DMOD;
    const int t = threadIdx.x;

    float v[4];
    float sum = 0.f;
#pragma unroll
    for (int j = 0; j < 4; j++) {
        v[j] = xf[t + 256 * j] + rz[t + 256 * j];
        sum += v[j];
    }
    red[t] = sum; __syncthreads();
    for (int s = 128; s > 0; s >>= 1) {
        if (t < s) red[t] += red[t + s];
        __syncthreads();
    }
    const float mu = red[0] * (1.f / DMOD);
    __syncthreads();

    float vs = 0.f;
#pragma unroll
    for (int j = 0; j < 4; j++) {
        const float d = v[j] - mu;
        vs += d * d;
    }
    red[t] = vs; __syncthreads();
    for (int s = 128; s > 0; s >>= 1) {
        if (t < s) red[t] += red[t + s];
        __syncthreads();
    }
    const float var = red[0] * (1.f / DMOD);
    const float inv = rsqrtf(var + 1e-5f);
#pragma unroll
    for (int j = 0; j < 4; j++) {
        const int cc = t + 256 * j;
        out[(size_t)r * DMOD + cc] = (v[j] - mu) * inv * gamma[cc] + beta[cc];
    }
}

// ---------------------------------------------------------------------------
extern "C" void kernel_launch(void* const* d_in, const int* in_sizes, int n_in,
                              void* d_out, int out_size)
{
    const float* q    = (const float*)d_in[0];
    const float* k    = (const float*)d_in[1];
    const float* v    = (const float*)d_in[2];
    const int*   mask = (const int*)  d_in[3];
    const float* gate = (const float*)d_in[4];
    const float* w_q  = (const float*)d_in[5];
    const float* b_q  = (const float*)d_in[6];
    const float* w_k  = (const float*)d_in[7];
    const float* b_k  = (const float*)d_in[8];
    const float* w_v  = (const float*)d_in[9];
    const float* b_v  = (const float*)d_in[10];
    const float* w_fc = (const float*)d_in[11];
    const float* b_fc = (const float*)d_in[12];
    const float* ln_g = (const float*)d_in[13];
    const float* ln_b = (const float*)d_in[14];
    float* out = (float*)d_out;

    float *p_qh, *p_kh, *p_vh, *p_ctx, *p_fc, *p_part, *p_inv, *p_attn_s, *p_outs;
    cudaGetSymbolAddress((void**)&p_qh,     g_qh);
    cudaGetSymbolAddress((void**)&p_kh,     g_kh);
    cudaGetSymbolAddress((void**)&p_vh,     g_vh);
    cudaGetSymbolAddress((void**)&p_ctx,    g_ctx);
    cudaGetSymbolAddress((void**)&p_fc,     g_fc);
    cudaGetSymbolAddress((void**)&p_part,   g_part);
    cudaGetSymbolAddress((void**)&p_inv,    g_invsum);
    cudaGetSymbolAddress((void**)&p_attn_s, g_attn);
    cudaGetSymbolAddress((void**)&p_outs,   g_outs);

    // Reference returns (out, attn).  Resolve destinations from out_size.
    float* attn_ptr;
    float* out_ptr;
    const long long osz = (long long)out_size;
    if (osz >= OUT_ELEMS + ATT_ELEMS) {        // concatenated tuple
        out_ptr  = out;
        attn_ptr = out + OUT_ELEMS;
    } else if (osz >= ATT_ELEMS) {             // attn only
        out_ptr  = p_outs;
        attn_ptr = out;
    } else {                                   // out only
        out_ptr  = out;
        attn_ptr = p_attn_s;
    }

    // 1) QKV projections (tf32 tensor cores)
    gemm_tf32<<<dim3(8, 32), 256>>>(q, w_q, b_q, p_qh, DMOD, NH * DKH, DKH);
    gemm_tf32<<<dim3(8, 32), 256>>>(k, w_k, b_k, p_kh, DMOD, NH * DKH, DKH);
    gemm_tf32<<<dim3(8, 32), 256>>>(v, w_v, b_v, p_vh, DMOD, NH * DVH, DVH);

    // 2) Scores + gate/mask + exp + row-sum partials (unnormalized attn)
    scores_tf32<<<dim3(8, 8, ZH), 256>>>(p_qh, p_kh, gate, mask, attn_ptr, p_part);

    // 3) rowsum partials -> 1/rowsum
    reduce_inv<<<256, 256>>>(p_part, p_inv);

    // 4) AV: normalize attn in place + ctx
    av_tf32<<<dim3(8, ZH), 256>>>(attn_ptr, p_inv, p_vh, p_ctx);

    // 5) FC projection
    gemm_tf32<<<dim3(8, 32), 256>>>(p_ctx, w_fc, b_fc, p_fc, DMOD, DMOD, DMOD);

    // 6) Residual + LayerNorm -> final out
    ln_kernel<<<4096, 256>>>(q, ln_g, ln_b, p_fc, out_ptr);
}